// round 1
// baseline (speedup 1.0000x reference)
#include <cuda_runtime.h>

#define S_  16
#define T_  400
#define F_  16
#define SF_ 250
#define G_  4
#define H1  32
#define H2  16

#define CS   10            // sf per CTA chunk
#define NCH  (SF_ / CS)    // 25 shuffled chunks (+1 plain chunk)
#define PSTRIDE 132        // padded row stride (words) for P slice in smem
#define OUT_S ((SF_ + 1) * T_)   // 100400 outputs per s

// smem layout (floats): Ps[T_*PSTRIDE] | W2[512] | b2[16] | b1eff[32] | W3[16]
#define SMEM_FLOATS (T_ * PSTRIDE + H1 * H2 + H2 + H1 + H2)
#define SMEM_BYTES  (SMEM_FLOATS * 4)

__device__ float g_W1eff[F_ * H1];
__device__ float g_b1eff[H1];
__device__ float g_P[S_ * T_ * G_ * H1];   // [s][t][g*32+c]  (13.1 MB scratch)

__device__ __forceinline__ float lrelu(float x) {
    // leaky_relu(x, 0.01) == max(x, 0.01*x)
    return fmaxf(x, 0.01f * x);
}

// ---------------------------------------------------------------------------
// Fold normalize into layer-1:  W1eff[j][c] = sum_i Sigma[i][j]*W1[i][c]
//                               b1eff[c]    = b1[c] - sum_j mu[j]*W1eff[j][c]
// ---------------------------------------------------------------------------
__global__ void prep_kernel(const float* __restrict__ Sig,
                            const float* __restrict__ W1,
                            const float* __restrict__ b1,
                            const float* __restrict__ mu) {
    int c = threadIdx.x;
    if (c >= H1) return;
    float bacc = 0.f;
    #pragma unroll
    for (int j = 0; j < F_; j++) {
        float acc = 0.f;
        #pragma unroll
        for (int i = 0; i < F_; i++) acc += Sig[i * F_ + j] * W1[i * H1 + c];
        g_W1eff[j * H1 + c] = acc;
        bacc += mu[j] * acc;
    }
    g_b1eff[c] = b1[c] - bacc;
}

// ---------------------------------------------------------------------------
// P table: P[s][t][g][c] = dot(obs[s,t,4g:4g+4], W1eff[4g:4g+4, c])
// grid = S_*T_ blocks, 128 threads = (g,c)
// ---------------------------------------------------------------------------
__global__ void ptab_kernel(const float* __restrict__ obs) {
    int st = blockIdx.x;
    int g  = threadIdx.x >> 5;
    int c  = threadIdx.x & 31;
    const float* x = obs + st * F_ + g * 4;
    float acc = 0.f;
    #pragma unroll
    for (int k = 0; k < 4; k++) acc += x[k] * g_W1eff[(g * 4 + k) * H1 + c];
    g_P[st * (G_ * H1) + g * H1 + c] = acc;
}

// ---------------------------------------------------------------------------
// Tail of the MLP: leaky(h1) -> 32x16 -> leaky -> 16x1 -> sigmoid
// ---------------------------------------------------------------------------
__device__ __forceinline__ float mlp_tail(const float4* __restrict__ h,
                                          const float* __restrict__ sW2,
                                          const float* __restrict__ sB2,
                                          const float* __restrict__ sW3,
                                          float b3v) {
    float a[H1];
    #pragma unroll
    for (int q = 0; q < 8; q++) {
        a[q * 4 + 0] = lrelu(h[q].x);
        a[q * 4 + 1] = lrelu(h[q].y);
        a[q * 4 + 2] = lrelu(h[q].z);
        a[q * 4 + 3] = lrelu(h[q].w);
    }
    float4 h2[4];
    h2[0] = *(const float4*)(sB2 + 0);
    h2[1] = *(const float4*)(sB2 + 4);
    h2[2] = *(const float4*)(sB2 + 8);
    h2[3] = *(const float4*)(sB2 + 12);
    #pragma unroll
    for (int i = 0; i < H1; i++) {
        float ai = a[i];
        const float* wr = sW2 + i * H2;
        float4 w0 = *(const float4*)(wr + 0);
        float4 w1 = *(const float4*)(wr + 4);
        float4 w2 = *(const float4*)(wr + 8);
        float4 w3 = *(const float4*)(wr + 12);
        h2[0].x += ai * w0.x; h2[0].y += ai * w0.y; h2[0].z += ai * w0.z; h2[0].w += ai * w0.w;
        h2[1].x += ai * w1.x; h2[1].y += ai * w1.y; h2[1].z += ai * w1.z; h2[1].w += ai * w1.w;
        h2[2].x += ai * w2.x; h2[2].y += ai * w2.y; h2[2].z += ai * w2.z; h2[2].w += ai * w2.w;
        h2[3].x += ai * w3.x; h2[3].y += ai * w3.y; h2[3].z += ai * w3.z; h2[3].w += ai * w3.w;
    }
    float z = b3v;
    #pragma unroll
    for (int j = 0; j < 4; j++) {
        float4 w = *(const float4*)(sW3 + j * 4);
        z += lrelu(h2[j].x) * w.x;
        z += lrelu(h2[j].y) * w.y;
        z += lrelu(h2[j].z) * w.z;
        z += lrelu(h2[j].w) * w.w;
    }
    return 1.f / (1.f + __expf(-z));
}

// ---------------------------------------------------------------------------
// Main kernel: grid.x = NCH+1 (last chunk = plain path), grid.y = s
// ---------------------------------------------------------------------------
__global__ __launch_bounds__(256)
void main_kernel(const int* __restrict__ perm,
                 const float* __restrict__ W2,
                 const float* __restrict__ b2,
                 const float* __restrict__ W3,
                 const float* __restrict__ b3,
                 float* __restrict__ out) {
    extern __shared__ float sm[];
    float* Ps  = sm;                       // [t][g*32+c], row stride PSTRIDE
    float* sW2 = sm + T_ * PSTRIDE;        // [i*16+j]
    float* sB2 = sW2 + H1 * H2;            // [16]
    float* sB1 = sB2 + H2;                 // [32]
    float* sW3 = sB1 + H1;                 // [16]

    const int s     = blockIdx.y;
    const int chunk = blockIdx.x;
    const int tid   = threadIdx.x;

    // Load this s's P slice (400 x 128 floats) into padded smem, vectorized.
    const float4* src = (const float4*)(g_P + s * T_ * (G_ * H1));
    for (int m = tid; m < T_ * 32; m += blockDim.x) {
        int t = m >> 5, q = m & 31;
        float4 v = src[t * 32 + q];
        *(float4*)(Ps + t * PSTRIDE + q * 4) = v;
    }
    for (int i = tid; i < H1 * H2; i += blockDim.x) sW2[i] = W2[i];
    if (tid < H2) sB2[tid] = b2[tid];
    if (tid < H1) sB1[tid] = g_b1eff[tid];
    if (tid < H2) sW3[tid] = W3[tid];
    __syncthreads();
    const float b3v = b3[0];

    float* outs = out + s * OUT_S;

    if (chunk < NCH) {
        // Shuffled rows: sf in [chunk*CS, chunk*CS+CS), all t.
        const int sf0 = chunk * CS;
        for (int r = tid; r < CS * T_; r += blockDim.x) {
            int sfl = r / T_;
            int t   = r - sfl * T_;
            int sf  = sf0 + sfl;
            int base = ((sf * G_) * S_ + s) * T_ + t;   // + g*S_*T_ for group g
            int t0 = perm[base];
            int t1 = perm[base + S_ * T_];
            int t2 = perm[base + 2 * S_ * T_];
            int t3 = perm[base + 3 * S_ * T_];

            const float4* p0 = (const float4*)(Ps + t0 * PSTRIDE + 0);
            const float4* p1 = (const float4*)(Ps + t1 * PSTRIDE + 32);
            const float4* p2 = (const float4*)(Ps + t2 * PSTRIDE + 64);
            const float4* p3 = (const float4*)(Ps + t3 * PSTRIDE + 96);

            float4 h[8];
            #pragma unroll
            for (int q = 0; q < 8; q++) {
                float4 a = p0[q], b = p1[q], c = p2[q], d = p3[q];
                float4 bb = *(const float4*)(sB1 + q * 4);
                h[q].x = a.x + b.x + c.x + d.x + bb.x;
                h[q].y = a.y + b.y + c.y + d.y + bb.y;
                h[q].z = a.z + b.z + c.z + d.z + bb.z;
                h[q].w = a.w + b.w + c.w + d.w + bb.w;
            }
            outs[T_ + sf * T_ + t] = mlp_tail(h, sW2, sB2, sW3, b3v);
        }
    } else {
        // Plain rows: all four group-gathers at the same t.
        for (int t = tid; t < T_; t += blockDim.x) {
            const float* row = Ps + t * PSTRIDE;
            float4 h[8];
            #pragma unroll
            for (int q = 0; q < 8; q++) {
                float4 a = *(const float4*)(row + 0  + q * 4);
                float4 b = *(const float4*)(row + 32 + q * 4);
                float4 c = *(const float4*)(row + 64 + q * 4);
                float4 d = *(const float4*)(row + 96 + q * 4);
                float4 bb = *(const float4*)(sB1 + q * 4);
                h[q].x = a.x + b.x + c.x + d.x + bb.x;
                h[q].y = a.y + b.y + c.y + d.y + bb.y;
                h[q].z = a.z + b.z + c.z + d.z + bb.z;
                h[q].w = a.w + b.w + c.w + d.w + bb.w;
            }
            outs[t] = mlp_tail(h, sW2, sB2, sW3, b3v);
        }
    }
}

// ---------------------------------------------------------------------------
extern "C" void kernel_launch(void* const* d_in, const int* in_sizes, int n_in,
                              void* d_out, int out_size) {
    const float* obs = (const float*)d_in[0];
    const float* mu  = (const float*)d_in[1];
    const float* Sig = (const float*)d_in[2];
    const int*   perm = (const int*)d_in[3];
    const float* W1 = (const float*)d_in[4];
    const float* b1 = (const float*)d_in[5];
    const float* W2 = (const float*)d_in[6];
    const float* b2 = (const float*)d_in[7];
    const float* W3 = (const float*)d_in[8];
    const float* b3 = (const float*)d_in[9];
    float* out = (float*)d_out;

    cudaFuncSetAttribute(main_kernel, cudaFuncAttributeMaxDynamicSharedMemorySize, SMEM_BYTES);

    prep_kernel<<<1, 32>>>(Sig, W1, b1, mu);
    ptab_kernel<<<S_ * T_, 128>>>(obs);
    dim3 grid(NCH + 1, S_);
    main_kernel<<<grid, 256, SMEM_BYTES>>>(perm, W2, b2, W3, b3, out);
}

// round 2
// speedup vs baseline: 5.7651x; 5.7651x over previous
#include <cuda_runtime.h>

#define S_  16
#define T_  400
#define F_  16
#define SF_ 250
#define G_  4
#define H1  32
#define H2  16

#define OBS_STRIDE 20                 // padded obs row stride (words): banks 4*(5t+g)%32
#define THREADS    384
#define CTAS_PER_S 9
#define ROWS_S     (T_ * (SF_ + 1))   // 100400 rows per s (idx = sfp*400+t, sfp=0 plain)
#define ROWS_CTA   ((ROWS_S + CTAS_PER_S - 1) / CTAS_PER_S)   // 11156

typedef unsigned long long ull;

__device__ __forceinline__ ull pk2(float a, float b) {
    ull r; asm("mov.b64 %0, {%1,%2};" : "=l"(r) : "f"(a), "f"(b)); return r;
}
__device__ __forceinline__ void upk(ull p, float& a, float& b) {
    asm("mov.b64 {%0,%1}, %2;" : "=f"(a), "=f"(b) : "l"(p));
}
__device__ __forceinline__ ull fma2(ull a, ull b, ull c) {
    ull d; asm("fma.rn.f32x2 %0, %1, %2, %3;" : "=l"(d) : "l"(a), "l"(b), "l"(c)); return d;
}
__device__ __forceinline__ float lrelu(float x) { return fmaxf(x, 0.01f * x); }

__global__ __launch_bounds__(THREADS, 1)
void fused_kernel(const float* __restrict__ obs,
                  const float* __restrict__ mu,
                  const float* __restrict__ Sig,
                  const int*   __restrict__ perm,
                  const float* __restrict__ W1,
                  const float* __restrict__ b1,
                  const float* __restrict__ W2,
                  const float* __restrict__ b2,
                  const float* __restrict__ W3,
                  const float* __restrict__ b3,
                  float* __restrict__ out) {
    __shared__ __align__(16) float sObs[T_ * OBS_STRIDE];  // 32000 B
    __shared__ __align__(16) float sW1[F_ * H1];           // W1eff [j][c], stride 32
    __shared__ __align__(16) float sW2[H1 * H2];           // [i][j], stride 16
    __shared__ __align__(16) float sB1[H1];
    __shared__ __align__(16) float sB2[H2];
    __shared__ __align__(16) float sW3[H2];

    const int s   = blockIdx.y;
    const int k   = blockIdx.x;
    const int tid = threadIdx.x;

    // ---- stage obs slice (padded) ----
    const float4* osrc = (const float4*)(obs + s * (T_ * F_));
    for (int m = tid; m < T_ * F_ / 4; m += THREADS) {
        int t = m >> 2, q = m & 3;
        *(float4*)(sObs + t * OBS_STRIDE + q * 4) = osrc[m];
    }
    // ---- W1eff = Sigma^T W1 (normalize folded into layer 1) ----
    for (int m = tid; m < F_ * H1; m += THREADS) {
        int j = m >> 5, c = m & 31;
        float acc = 0.f;
        #pragma unroll
        for (int i = 0; i < F_; i++) acc += Sig[i * F_ + j] * W1[i * H1 + c];
        sW1[j * H1 + c] = acc;
    }
    // ---- b1eff = b1 - mu^T W1eff ----
    if (tid < H1) {
        int c = tid;
        float bacc = 0.f;
        #pragma unroll
        for (int j = 0; j < F_; j++) {
            float wj = 0.f;
            #pragma unroll
            for (int i = 0; i < F_; i++) wj += Sig[i * F_ + j] * W1[i * H1 + c];
            bacc += mu[j] * wj;
        }
        sB1[c] = b1[c] - bacc;
    }
    for (int m = tid; m < H1 * H2; m += THREADS) sW2[m] = W2[m];
    if (tid < H2) sB2[tid] = b2[tid];
    if (tid < H2) sW3[tid] = W3[tid];
    __syncthreads();

    const float b3v = b3[0];
    const int rowsBeg = k * ROWS_CTA;
    const int rowsEnd = (rowsBeg + ROWS_CTA < ROWS_S) ? rowsBeg + ROWS_CTA : ROWS_S;
    float* outS = out + s * ROWS_S;

    for (int idxA = rowsBeg + tid; idxA < rowsEnd; idxA += 2 * THREADS) {
        int idxB = idxA + THREADS;
        const bool hasB = (idxB < rowsEnd);
        if (!hasB) idxB = idxA;   // duplicate row A, discard store

        // ---- decode + perm gather indices ----
        int sfpA = idxA / T_, tA = idxA - sfpA * T_;
        int sfpB = idxB / T_, tB = idxB - sfpB * T_;
        int ta0, ta1, ta2, ta3, tb0, tb1, tb2, tb3;
        if (sfpA == 0) { ta0 = ta1 = ta2 = ta3 = tA; }
        else {
            int base = ((sfpA - 1) * (G_ * S_) + s) * T_ + tA;
            ta0 = perm[base];
            ta1 = perm[base + S_ * T_];
            ta2 = perm[base + 2 * S_ * T_];
            ta3 = perm[base + 3 * S_ * T_];
        }
        if (sfpB == 0) { tb0 = tb1 = tb2 = tb3 = tB; }
        else {
            int base = ((sfpB - 1) * (G_ * S_) + s) * T_ + tB;
            tb0 = perm[base];
            tb1 = perm[base + S_ * T_];
            tb2 = perm[base + 2 * S_ * T_];
            tb3 = perm[base + 3 * S_ * T_];
        }

        // ---- gather shuffled feature vectors (4 x float4 per row) ----
        float xA[16], xB[16];
        *(float4*)(xA + 0)  = *(const float4*)(sObs + ta0 * OBS_STRIDE + 0);
        *(float4*)(xA + 4)  = *(const float4*)(sObs + ta1 * OBS_STRIDE + 4);
        *(float4*)(xA + 8)  = *(const float4*)(sObs + ta2 * OBS_STRIDE + 8);
        *(float4*)(xA + 12) = *(const float4*)(sObs + ta3 * OBS_STRIDE + 12);
        *(float4*)(xB + 0)  = *(const float4*)(sObs + tb0 * OBS_STRIDE + 0);
        *(float4*)(xB + 4)  = *(const float4*)(sObs + tb1 * OBS_STRIDE + 4);
        *(float4*)(xB + 8)  = *(const float4*)(sObs + tb2 * OBS_STRIDE + 8);
        *(float4*)(xB + 12) = *(const float4*)(sObs + tb3 * OBS_STRIDE + 12);

        // ---- layer 1: h1[32] = W1eff^T x + b1eff (f32x2, j-packed) ----
        ull hA[16], hB[16];
        {
            const ull* pb = (const ull*)sB1;
            #pragma unroll
            for (int p = 0; p < 16; p++) { hA[p] = pb[p]; hB[p] = pb[p]; }
        }
        #pragma unroll
        for (int j = 0; j < F_; j++) {
            ull aj = pk2(xA[j], xA[j]);
            ull bj = pk2(xB[j], xB[j]);
            const ulonglong2* w = (const ulonglong2*)(sW1 + j * H1);
            #pragma unroll
            for (int q = 0; q < 8; q++) {
                ulonglong2 ww = w[q];
                hA[2 * q]     = fma2(aj, ww.x, hA[2 * q]);
                hA[2 * q + 1] = fma2(aj, ww.y, hA[2 * q + 1]);
                hB[2 * q]     = fma2(bj, ww.x, hB[2 * q]);
                hB[2 * q + 1] = fma2(bj, ww.y, hB[2 * q + 1]);
            }
        }

        // ---- leaky relu ----
        float aA[H1], aB[H1];
        #pragma unroll
        for (int p = 0; p < 16; p++) {
            float u, v;
            upk(hA[p], u, v); aA[2 * p] = lrelu(u); aA[2 * p + 1] = lrelu(v);
            upk(hB[p], u, v); aB[2 * p] = lrelu(u); aB[2 * p + 1] = lrelu(v);
        }

        // ---- layer 2: h2[16] = W2^T a + b2 (f32x2, j-packed) ----
        ull cA[8], cB[8];
        {
            const ull* pb = (const ull*)sB2;
            #pragma unroll
            for (int p = 0; p < 8; p++) { cA[p] = pb[p]; cB[p] = pb[p]; }
        }
        #pragma unroll
        for (int i = 0; i < H1; i++) {
            ull ai = pk2(aA[i], aA[i]);
            ull bi = pk2(aB[i], aB[i]);
            const ulonglong2* w = (const ulonglong2*)(sW2 + i * H2);
            #pragma unroll
            for (int q = 0; q < 4; q++) {
                ulonglong2 ww = w[q];
                cA[2 * q]     = fma2(ai, ww.x, cA[2 * q]);
                cA[2 * q + 1] = fma2(ai, ww.y, cA[2 * q + 1]);
                cB[2 * q]     = fma2(bi, ww.x, cB[2 * q]);
                cB[2 * q + 1] = fma2(bi, ww.y, cB[2 * q + 1]);
            }
        }

        // ---- layer 3 + sigmoid ----
        float zA = b3v, zB = b3v;
        #pragma unroll
        for (int p = 0; p < 8; p++) {
            float u, v;
            upk(cA[p], u, v); zA += lrelu(u) * sW3[2 * p] + lrelu(v) * sW3[2 * p + 1];
            upk(cB[p], u, v); zB += lrelu(u) * sW3[2 * p] + lrelu(v) * sW3[2 * p + 1];
        }
        outS[idxA] = 1.f / (1.f + __expf(-zA));
        if (hasB) outS[idxB] = 1.f / (1.f + __expf(-zB));
    }
}

extern "C" void kernel_launch(void* const* d_in, const int* in_sizes, int n_in,
                              void* d_out, int out_size) {
    const float* obs  = (const float*)d_in[0];
    const float* mu   = (const float*)d_in[1];
    const float* Sig  = (const float*)d_in[2];
    const int*   perm = (const int*)d_in[3];
    const float* W1   = (const float*)d_in[4];
    const float* b1   = (const float*)d_in[5];
    const float* W2   = (const float*)d_in[6];
    const float* b2   = (const float*)d_in[7];
    const float* W3   = (const float*)d_in[8];
    const float* b3   = (const float*)d_in[9];
    float* out = (float*)d_out;

    dim3 grid(CTAS_PER_S, S_);
    fused_kernel<<<grid, THREADS>>>(obs, mu, Sig, perm, W1, b1, W2, b2, W3, b3, out);
}